// round 1
// baseline (speedup 1.0000x reference)
#include <cuda_runtime.h>
#include <math.h>

#define N_RAYS_TOTAL 32768
#define HID 256
#define TILE_M 64
#define NTHREADS 256
#define KC 16

#define EPS 1e-3f
#define MAX_RAY 3.5f
#define SPHERE_R 0.7f
#define SCALE_TR 1.41421356237309515f  /* sqrt(2), rounds to fp32 nearest */
#define COS30 0.8660254037844387f

// ---------------- persistent ray state (no allocations allowed) ----------------
__device__ float g_pos[N_RAYS_TOTAL * 3];
__device__ float g_dir[N_RAYS_TOTAL * 3];
__device__ float g_t[N_RAYS_TOTAL];
__device__ int   g_active[N_RAYS_TOTAL];
__device__ float g_c1[HID];

// ---------------- c1[j] = b1[j] + sum_i lat[i] * W1[3+i][j] ----------------
__global__ void prep_c1_kernel(const float* __restrict__ lat_geo,
                               const float* __restrict__ lat_exp,
                               const float* __restrict__ lat_app,
                               const float* __restrict__ W1,
                               const float* __restrict__ b1) {
    __shared__ float lat[484];
    int tid = threadIdx.x;
    if (tid < 256) lat[tid] = lat_geo[tid];
    if (tid < 100) lat[256 + tid] = lat_exp[tid];
    if (tid < 128) lat[356 + tid] = lat_app[tid];
    __syncthreads();
    // 256 threads, one output column each; W1 row reads are coalesced.
    float c = b1[tid];
#pragma unroll 4
    for (int i = 0; i < 484; i++) {
        c = fmaf(lat[i], W1[(3 + i) * 256 + tid], c);
    }
    g_c1[tid] = c;
}

// ---------------- ray setup: start position, direction, t=0, active=1 ----------------
__global__ void init_rays_kernel() {
    int r = blockIdx.x * blockDim.x + threadIdx.x;
    if (r >= N_RAYS_TOTAL) return;
    int view = r >> 14;          // 0: rho=-30, 1: rho=+30
    int p = r & 16383;
    int i = p >> 7;              // u index (meshgrid 'ij', reshape -> i*128+j)
    int j = p & 127;             // v index

    float u = (i + 0.5f) * (1.0f / 128.0f) - 0.5f;
    float v = 0.5f - (j + 0.5f) * (1.0f / 128.0f);

    float dx = u, dy = v, dz = -1.0f;
    float inv = 1.0f / sqrtf(dx * dx + dy * dy + dz * dz);
    dx *= inv; dy *= inv; dz *= inv;

    float s = view ? 0.5f : -0.5f;   // sin(+-30 deg) exactly
    const float c = COS30;
    // dirs = R * d  (d @ R.T)
    float rx = c * dx + s * dz;
    float ry = dy;
    float rz = -s * dx + c * dz;
    // cam = 2.2 * R*[0,0,1] = 2.2*[s,0,c]; start = cam + (focal+dist-1)*dir = cam + 2.2*dir
    float sx = 2.2f * s + 2.2f * rx;
    float sy = 0.0f   + 2.2f * ry;
    float sz = 2.2f * c + 2.2f * rz;

    g_pos[r * 3 + 0] = sx;
    g_pos[r * 3 + 1] = sy;
    g_pos[r * 3 + 2] = sz;
    g_dir[r * 3 + 0] = rx;
    g_dir[r * 3 + 1] = ry;
    g_dir[r * 3 + 2] = rz;
    g_t[r] = 0.0f;
    g_active[r] = 1;
}

// ---------------- one full SDF eval (+ trace update OR final mask/output) ----------------
// SMEM layout (floats):
//   h1s   [256][64]      16384
//   w2s   [KC][256]       4096
//   w1r   [3][256]         768
//   c1s   [256]            256
//   b2s   [256]            256
//   w3s   [256]            256
//   posS  [64*3]           192
//   dirS  [64*3]           192
//   pS    [64]              64
#define SMEM_FLOATS (16384 + 4096 + 768 + 256 + 256 + 256 + 192 + 192 + 64)
#define SMEM_BYTES  (SMEM_FLOATS * 4)

__global__ void __launch_bounds__(NTHREADS, 2)
eval_kernel(const float* __restrict__ W1,
            const float* __restrict__ W2,
            const float* __restrict__ b2,
            const float* __restrict__ W3,
            const float* __restrict__ b3,
            int final_pass,
            float* __restrict__ out) {
    extern __shared__ float sm[];
    float* h1s  = sm;                 // [k][r] layout: k*64 + r
    float* w2s  = h1s + 16384;        // [k_local][n]: k*256 + n
    float* w1r  = w2s + 4096;         // 3 rows of W1
    float* c1s  = w1r + 768;
    float* b2s  = c1s + 256;
    float* w3s  = b2s + 256;
    float* posS = w3s + 256;          // [r*3+c]
    float* dirS = posS + 192;
    float* pS   = dirS + 192;

    const int tid = threadIdx.x;
    const int base = blockIdx.x * TILE_M;

    // ---- stage small constants + ray state ----
    {
        w1r[tid]       = W1[tid];          // row 0
        w1r[256 + tid] = W1[256 + tid];    // row 1
        w1r[512 + tid] = W1[512 + tid];    // row 2
        c1s[tid] = g_c1[tid];
        b2s[tid] = b2[tid];
        w3s[tid] = W3[tid * 4];            // W3[:,0] only (color is dead code)
        if (tid < 192) {
            posS[tid] = g_pos[base * 3 + tid];
            dirS[tid] = g_dir[base * 3 + tid];
        }
    }
    __syncthreads();

    // ---- GEMM1 (K=3) + c1 + relu -> h1s ----
    {
        int r = tid & 63;
        int k0 = tid >> 6;                 // warp-uniform
        float px = posS[r * 3 + 0];
        float py = posS[r * 3 + 1];
        float pz = posS[r * 3 + 2];
#pragma unroll 8
        for (int kk = 0; kk < 64; kk++) {
            int k = k0 + kk * 4;
            float h = fmaf(px, w1r[k],
                      fmaf(py, w1r[256 + k],
                      fmaf(pz, w1r[512 + k], c1s[k])));
            h1s[k * 64 + r] = fmaxf(h, 0.0f);
        }
    }
    __syncthreads();

    // ---- GEMM2: h2 = relu(h1 @ W2 + b2), register-blocked 8x8 ----
    const int cg = tid & 31;   // 32 column groups of 8 (lane id)
    const int rg = tid >> 5;   // 8 ray groups of 8 (warp id)

    float acc[8][8];
#pragma unroll
    for (int i = 0; i < 8; i++)
#pragma unroll
        for (int j = 0; j < 8; j++) acc[i][j] = 0.0f;

    for (int kc = 0; kc < HID; kc += KC) {
        // stage W2 chunk [KC][256], coalesced float4
        {
            const float4* src = (const float4*)(W2 + kc * 256);
            float4* dst = (float4*)w2s;
#pragma unroll
            for (int i = tid; i < KC * 64; i += NTHREADS) dst[i] = src[i];
        }
        __syncthreads();

#pragma unroll
        for (int k = 0; k < KC; k++) {
            const float* hrow = &h1s[(kc + k) * 64 + rg * 8];  // warp-uniform addr -> broadcast
            float4 a0 = *(const float4*)(hrow);
            float4 a1 = *(const float4*)(hrow + 4);
            const float* wrow = &w2s[k * 256 + cg * 8];
            float4 b0 = *(const float4*)(wrow);
            float4 b1 = *(const float4*)(wrow + 4);
            float a[8] = {a0.x, a0.y, a0.z, a0.w, a1.x, a1.y, a1.z, a1.w};
            float b[8] = {b0.x, b0.y, b0.z, b0.w, b1.x, b1.y, b1.z, b1.w};
#pragma unroll
            for (int i = 0; i < 8; i++)
#pragma unroll
                for (int j = 0; j < 8; j++)
                    acc[i][j] = fmaf(a[i], b[j], acc[i][j]);
        }
        __syncthreads();
    }

    // ---- GEMV3 (only column 0 of W3 matters) with warp reduction ----
    float p[8];
#pragma unroll
    for (int i = 0; i < 8; i++) p[i] = 0.0f;
#pragma unroll
    for (int i = 0; i < 8; i++) {
#pragma unroll
        for (int j = 0; j < 8; j++) {
            float h2 = fmaxf(acc[i][j] + b2s[cg * 8 + j], 0.0f);
            p[i] = fmaf(h2, w3s[cg * 8 + j], p[i]);
        }
    }
#pragma unroll
    for (int off = 16; off > 0; off >>= 1) {
#pragma unroll
        for (int i = 0; i < 8; i++)
            p[i] += __shfl_xor_sync(0xFFFFFFFFu, p[i], off);
    }
    if (cg == 0) {
#pragma unroll
        for (int i = 0; i < 8; i++) pS[rg * 8 + i] = p[i];
    }
    __syncthreads();

    // ---- per-ray epilogue: sdf, hit test, trace update or final output ----
    if (tid < TILE_M) {
        int ray = base + tid;
        float px = posS[tid * 3 + 0];
        float py = posS[tid * 3 + 1];
        float pz = posS[tid * 3 + 2];
        float out0 = pS[tid] + b3[0];
        float d = sqrtf(px * px + py * py + pz * pz) - SPHERE_R + out0;
        bool hit = fabsf(d) < EPS;

        if (final_pass) {
            out[ray * 3 + 0] = hit ? px : 0.0f;
            out[ray * 3 + 1] = hit ? py : 0.0f;
            out[ray * 3 + 2] = hit ? pz : 0.0f;
        } else {
            int act = g_active[ray];
            float adv = (act && !hit) ? SCALE_TR * d : 0.0f;
            px = fmaf(adv, dirS[tid * 3 + 0], px);
            py = fmaf(adv, dirS[tid * 3 + 1], py);
            pz = fmaf(adv, dirS[tid * 3 + 2], pz);
            float tt = g_t[ray] + adv;
            g_pos[ray * 3 + 0] = px;
            g_pos[ray * 3 + 1] = py;
            g_pos[ray * 3 + 2] = pz;
            g_t[ray] = tt;
            g_active[ray] = (act && !hit && (tt < MAX_RAY)) ? 1 : 0;
        }
    }
}

// ---------------- launch ----------------
extern "C" void kernel_launch(void* const* d_in, const int* in_sizes, int n_in,
                              void* d_out, int out_size) {
    const float* lat_geo = (const float*)d_in[0];
    const float* lat_exp = (const float*)d_in[1];
    const float* lat_app = (const float*)d_in[2];
    const float* W1      = (const float*)d_in[3];
    const float* b1      = (const float*)d_in[4];
    const float* W2      = (const float*)d_in[5];
    const float* b2      = (const float*)d_in[6];
    const float* W3      = (const float*)d_in[7];
    const float* b3      = (const float*)d_in[8];
    float* out = (float*)d_out;

    cudaFuncSetAttribute(eval_kernel,
                         cudaFuncAttributeMaxDynamicSharedMemorySize, SMEM_BYTES);

    prep_c1_kernel<<<1, 256>>>(lat_geo, lat_exp, lat_app, W1, b1);
    init_rays_kernel<<<N_RAYS_TOTAL / 256, 256>>>();

    const int nblocks = N_RAYS_TOTAL / TILE_M;  // 512
    for (int s = 0; s < 6; s++) {
        eval_kernel<<<nblocks, NTHREADS, SMEM_BYTES>>>(W1, W2, b2, W3, b3, 0, out);
    }
    eval_kernel<<<nblocks, NTHREADS, SMEM_BYTES>>>(W1, W2, b2, W3, b3, 1, out);
}

// round 2
// speedup vs baseline: 1.0786x; 1.0786x over previous
#include <cuda_runtime.h>
#include <math.h>

#define N_RAYS_TOTAL 32768
#define HID 256
#define TILE_M 64
#define NTHREADS 256
#define KC 16

#define EPS 1e-3f
#define MAX_RAY 3.5f
#define SPHERE_R 0.7f
#define SCALE_TR 1.41421356237309515f
#define COS30 0.8660254037844387f

typedef unsigned long long u64;

// packed fp32x2 FMA (SASS FFMA2) — 2 lane-FMAs per fma-pipe slot
#define FMA2(acc, a, b) \
    asm("fma.rn.f32x2 %0, %1, %2, %0;" : "+l"(acc) : "l"(a), "l"(b))
#define SPLAT2(dst, f) \
    asm("mov.b64 %0, {%1, %1};" : "=l"(dst) : "r"(__float_as_uint(f)))
#define UNPACK2(lo, hi, v) \
    asm("mov.b64 {%0, %1}, %2;" : "=r"(lo), "=r"(hi) : "l"(v))

// ---------------- persistent ray state ----------------
__device__ float g_pos[N_RAYS_TOTAL * 3];
__device__ float g_dir[N_RAYS_TOTAL * 3];
__device__ float g_t[N_RAYS_TOTAL];
__device__ int   g_active[N_RAYS_TOTAL];
__device__ float g_c1[HID];

// ---------------- c1[j] = b1[j] + sum_i lat[i] * W1[3+i][j] ----------------
__global__ void prep_c1_kernel(const float* __restrict__ lat_geo,
                               const float* __restrict__ lat_exp,
                               const float* __restrict__ lat_app,
                               const float* __restrict__ W1,
                               const float* __restrict__ b1) {
    __shared__ float lat[484];
    int tid = threadIdx.x;
    if (tid < 256) lat[tid] = lat_geo[tid];
    if (tid < 100) lat[256 + tid] = lat_exp[tid];
    if (tid < 128) lat[356 + tid] = lat_app[tid];
    __syncthreads();
    float c = b1[tid];
#pragma unroll 4
    for (int i = 0; i < 484; i++) {
        c = fmaf(lat[i], W1[(3 + i) * 256 + tid], c);
    }
    g_c1[tid] = c;
}

// ---------------- ray setup ----------------
__global__ void init_rays_kernel() {
    int r = blockIdx.x * blockDim.x + threadIdx.x;
    if (r >= N_RAYS_TOTAL) return;
    int view = r >> 14;
    int p = r & 16383;
    int i = p >> 7;
    int j = p & 127;

    float u = (i + 0.5f) * (1.0f / 128.0f) - 0.5f;
    float v = 0.5f - (j + 0.5f) * (1.0f / 128.0f);

    float dx = u, dy = v, dz = -1.0f;
    float inv = 1.0f / sqrtf(dx * dx + dy * dy + dz * dz);
    dx *= inv; dy *= inv; dz *= inv;

    float s = view ? 0.5f : -0.5f;
    const float c = COS30;
    float rx = c * dx + s * dz;
    float ry = dy;
    float rz = -s * dx + c * dz;
    float sx = 2.2f * s + 2.2f * rx;
    float sy = 2.2f * ry;
    float sz = 2.2f * c + 2.2f * rz;

    g_pos[r * 3 + 0] = sx;
    g_pos[r * 3 + 1] = sy;
    g_pos[r * 3 + 2] = sz;
    g_dir[r * 3 + 0] = rx;
    g_dir[r * 3 + 1] = ry;
    g_dir[r * 3 + 2] = rz;
    g_t[r] = 0.0f;
    g_active[r] = 1;
}

// ---------------- one full SDF eval ----------------
#define SMEM_FLOATS (16384 + 4096 + 768 + 256 + 256 + 256 + 192 + 192 + 64)
#define SMEM_BYTES  (SMEM_FLOATS * 4)

__global__ void __launch_bounds__(NTHREADS, 2)
eval_kernel(const float* __restrict__ W1,
            const float* __restrict__ W2,
            const float* __restrict__ b2,
            const float* __restrict__ W3,
            const float* __restrict__ b3,
            int final_pass,
            float* __restrict__ out) {
    extern __shared__ float sm[];
    float* h1s  = sm;                 // [k][r]: k*64 + r
    float* w2s  = h1s + 16384;        // [k_local][n]: k*256 + n
    float* w1r  = w2s + 4096;
    float* c1s  = w1r + 768;
    float* b2s  = c1s + 256;
    float* w3s  = b2s + 256;
    float* posS = w3s + 256;
    float* dirS = posS + 192;
    float* pS   = dirS + 192;

    const int tid = threadIdx.x;
    const int base = blockIdx.x * TILE_M;

    // ---- stage small constants + ray state ----
    {
        w1r[tid]       = W1[tid];
        w1r[256 + tid] = W1[256 + tid];
        w1r[512 + tid] = W1[512 + tid];
        c1s[tid] = g_c1[tid];
        b2s[tid] = b2[tid];
        w3s[tid] = W3[tid * 4];            // only W3[:,0] is live
        if (tid < 192) {
            posS[tid] = g_pos[base * 3 + tid];
            dirS[tid] = g_dir[base * 3 + tid];
        }
    }
    __syncthreads();

    // ---- GEMM1 (K=3) + c1 + relu -> h1s ----
    {
        int r = tid & 63;
        int k0 = tid >> 6;
        float px = posS[r * 3 + 0];
        float py = posS[r * 3 + 1];
        float pz = posS[r * 3 + 2];
#pragma unroll 8
        for (int kk = 0; kk < 64; kk++) {
            int k = k0 + kk * 4;
            float h = fmaf(px, w1r[k],
                      fmaf(py, w1r[256 + k],
                      fmaf(pz, w1r[512 + k], c1s[k])));
            h1s[k * 64 + r] = fmaxf(h, 0.0f);
        }
    }
    __syncthreads();

    // ---- GEMM2 via packed fp32x2: each thread = 8 rays x (4 + 4) cols ----
    // lane cg owns cols [cg*4, cg*4+4) and [128+cg*4, 128+cg*4+4)  (conflict-free LDS.128)
    const int cg = tid & 31;
    const int rg = tid >> 5;

    u64 acc[8][4];
#pragma unroll
    for (int i = 0; i < 8; i++)
#pragma unroll
        for (int j = 0; j < 4; j++) acc[i][j] = 0ull;

    for (int kc = 0; kc < HID; kc += KC) {
        {
            const float4* src = (const float4*)(W2 + kc * 256);
            float4* dst = (float4*)w2s;
#pragma unroll
            for (int i = tid; i < KC * 64; i += NTHREADS) dst[i] = src[i];
        }
        __syncthreads();

#pragma unroll
        for (int k = 0; k < KC; k++) {
            // a: 8 h1 values for this warp's ray group (broadcast LDS.128), splat to f32x2
            const float* hrow = &h1s[(kc + k) * 64 + rg * 8];
            float4 a03 = *(const float4*)(hrow);
            float4 a47 = *(const float4*)(hrow + 4);
            u64 as[8];
            SPLAT2(as[0], a03.x); SPLAT2(as[1], a03.y);
            SPLAT2(as[2], a03.z); SPLAT2(as[3], a03.w);
            SPLAT2(as[4], a47.x); SPLAT2(as[5], a47.y);
            SPLAT2(as[6], a47.z); SPLAT2(as[7], a47.w);

            // b: two conflict-free 16B groups (4 packed pairs)
            const float* wrow = &w2s[k * 256];
            ulonglong2 bb0 = *(const ulonglong2*)(wrow + cg * 4);
            ulonglong2 bb1 = *(const ulonglong2*)(wrow + 128 + cg * 4);
            u64 b[4] = {bb0.x, bb0.y, bb1.x, bb1.y};

#pragma unroll
            for (int i = 0; i < 8; i++) {
                FMA2(acc[i][0], as[i], b[0]);
                FMA2(acc[i][1], as[i], b[1]);
                FMA2(acc[i][2], as[i], b[2]);
                FMA2(acc[i][3], as[i], b[3]);
            }
        }
        __syncthreads();
    }

    // ---- GEMV3 (col 0 of W3) with warp reduction ----
    float p[8];
#pragma unroll
    for (int i = 0; i < 8; i++) p[i] = 0.0f;
#pragma unroll
    for (int i = 0; i < 8; i++) {
#pragma unroll
        for (int jp = 0; jp < 4; jp++) {
            int col = (jp < 2) ? (cg * 4 + jp * 2) : (128 + cg * 4 + (jp - 2) * 2);
            unsigned int lo, hi;
            UNPACK2(lo, hi, acc[i][jp]);
            float h2a = fmaxf(__uint_as_float(lo) + b2s[col], 0.0f);
            float h2b = fmaxf(__uint_as_float(hi) + b2s[col + 1], 0.0f);
            p[i] = fmaf(h2a, w3s[col], p[i]);
            p[i] = fmaf(h2b, w3s[col + 1], p[i]);
        }
    }
#pragma unroll
    for (int off = 16; off > 0; off >>= 1) {
#pragma unroll
        for (int i = 0; i < 8; i++)
            p[i] += __shfl_xor_sync(0xFFFFFFFFu, p[i], off);
    }
    if (cg == 0) {
#pragma unroll
        for (int i = 0; i < 8; i++) pS[rg * 8 + i] = p[i];
    }
    __syncthreads();

    // ---- per-ray epilogue ----
    if (tid < TILE_M) {
        int ray = base + tid;
        float px = posS[tid * 3 + 0];
        float py = posS[tid * 3 + 1];
        float pz = posS[tid * 3 + 2];
        float out0 = pS[tid] + b3[0];
        float d = sqrtf(px * px + py * py + pz * pz) - SPHERE_R + out0;
        bool hit = fabsf(d) < EPS;

        if (final_pass) {
            out[ray * 3 + 0] = hit ? px : 0.0f;
            out[ray * 3 + 1] = hit ? py : 0.0f;
            out[ray * 3 + 2] = hit ? pz : 0.0f;
        } else {
            int act = g_active[ray];
            float adv = (act && !hit) ? SCALE_TR * d : 0.0f;
            px = fmaf(adv, dirS[tid * 3 + 0], px);
            py = fmaf(adv, dirS[tid * 3 + 1], py);
            pz = fmaf(adv, dirS[tid * 3 + 2], pz);
            float tt = g_t[ray] + adv;
            g_pos[ray * 3 + 0] = px;
            g_pos[ray * 3 + 1] = py;
            g_pos[ray * 3 + 2] = pz;
            g_t[ray] = tt;
            g_active[ray] = (act && !hit && (tt < MAX_RAY)) ? 1 : 0;
        }
    }
}

// ---------------- launch ----------------
extern "C" void kernel_launch(void* const* d_in, const int* in_sizes, int n_in,
                              void* d_out, int out_size) {
    const float* lat_geo = (const float*)d_in[0];
    const float* lat_exp = (const float*)d_in[1];
    const float* lat_app = (const float*)d_in[2];
    const float* W1      = (const float*)d_in[3];
    const float* b1      = (const float*)d_in[4];
    const float* W2      = (const float*)d_in[5];
    const float* b2      = (const float*)d_in[6];
    const float* W3      = (const float*)d_in[7];
    const float* b3      = (const float*)d_in[8];
    float* out = (float*)d_out;

    cudaFuncSetAttribute(eval_kernel,
                         cudaFuncAttributeMaxDynamicSharedMemorySize, SMEM_BYTES);

    prep_c1_kernel<<<1, 256>>>(lat_geo, lat_exp, lat_app, W1, b1);
    init_rays_kernel<<<N_RAYS_TOTAL / 256, 256>>>();

    const int nblocks = N_RAYS_TOTAL / TILE_M;  // 512
    for (int s = 0; s < 6; s++) {
        eval_kernel<<<nblocks, NTHREADS, SMEM_BYTES>>>(W1, W2, b2, W3, b3, 0, out);
    }
    eval_kernel<<<nblocks, NTHREADS, SMEM_BYTES>>>(W1, W2, b2, W3, b3, 1, out);
}